// round 1
// baseline (speedup 1.0000x reference)
#include <cuda_runtime.h>
#include <cuda_bf16.h>

#define N_NODES 100000
#define N_EDGES 1600000
#define IN_DIM  64
#define HID     128   // 2*OUT_DIM
#define OUT_DIM 64
#define BN_EPS  1e-5f

// ---------------- scratch (device globals; no allocation allowed) ----------
__device__ float g_ns[N_NODES * IN_DIM];     // neighbor sums   25.6 MB
__device__ float g_h1[N_NODES * HID];        // post-GEMM1      51.2 MB
__device__ float g_h2[N_NODES * OUT_DIM];    // post-GEMM2      25.6 MB
// stats: [0,128) sum1, [128,256) sq1, [256,320) sum2, [320,384) sq2
__device__ float g_stats[384];

// ---------------- K0: zero scratch -----------------------------------------
__global__ void k_zero() {
    long long i = (long long)blockIdx.x * blockDim.x + threadIdx.x;
    long long tot = (long long)N_NODES * IN_DIM;
    if (i < tot) g_ns[i] = 0.0f;
    if (i < 384) g_stats[i] = 0.0f;
}

// ---------------- K1: edge scatter-add (16 lanes/edge, v4 red) -------------
__global__ void k_scatter(const float* __restrict__ x,
                          const int* __restrict__ src,
                          const int* __restrict__ dst) {
    unsigned gid = blockIdx.x * blockDim.x + threadIdx.x;
    const unsigned TOT = N_EDGES * 16u;       // 16 float4 per edge row
    if (gid >= TOT) return;
    unsigned e = gid >> 4;
    unsigned q = gid & 15u;
    int s = src[e];
    int d = dst[e];
    const float4* x4 = reinterpret_cast<const float4*>(x);
    float4 v = x4[(long long)s * 16 + q];
    float* p = g_ns + ((long long)d * 64 + q * 4);
    asm volatile("red.global.add.v4.f32 [%0], {%1, %2, %3, %4};"
                 :: "l"(p), "f"(v.x), "f"(v.y), "f"(v.z), "f"(v.w)
                 : "memory");
}

// ---------------- K2: h1 = ((1+eps)*x + ns) @ W1 + b1 ----------------------
// block: 256 threads = 32 rows x 8 col-groups of 16
__global__ void k_gemm1(const float* __restrict__ x,
                        const float* __restrict__ eps_p,
                        const float* __restrict__ W1,
                        const float* __restrict__ b1) {
    __shared__ float s_W[IN_DIM * HID];    // 32 KB
    __shared__ float s_b[HID];
    __shared__ float s_c[32 * 65];         // padded combined tile

    int tid = threadIdx.x;
    // stage weights
    #pragma unroll
    for (int i = 0; i < 32; i++) s_W[tid + i * 256] = W1[tid + i * 256];
    if (tid < HID) s_b[tid] = b1[tid];

    float ep1 = 1.0f + eps_p[0];
    int base = blockIdx.x * 32;
    // stage combined input tile: 32x64 = 2048 elems, 8 per thread
    #pragma unroll
    for (int i = 0; i < 8; i++) {
        int idx = tid + i * 256;
        int r = idx >> 6, k = idx & 63;
        long long g = (long long)(base + r) * 64 + k;
        s_c[r * 65 + k] = ep1 * x[g] + g_ns[g];
    }
    __syncthreads();

    int row = tid >> 3;
    int col0 = (tid & 7) * 16;
    float acc[16];
    #pragma unroll
    for (int j = 0; j < 16; j++) acc[j] = s_b[col0 + j];

    const float* cr = s_c + row * 65;
    #pragma unroll 4
    for (int k = 0; k < IN_DIM; k++) {
        float a = cr[k];
        const float4* w4 = reinterpret_cast<const float4*>(s_W + k * HID + col0);
        float4 w0 = w4[0], w1 = w4[1], w2 = w4[2], w3 = w4[3];
        acc[0]  += a * w0.x; acc[1]  += a * w0.y; acc[2]  += a * w0.z; acc[3]  += a * w0.w;
        acc[4]  += a * w1.x; acc[5]  += a * w1.y; acc[6]  += a * w1.z; acc[7]  += a * w1.w;
        acc[8]  += a * w2.x; acc[9]  += a * w2.y; acc[10] += a * w2.z; acc[11] += a * w2.w;
        acc[12] += a * w3.x; acc[13] += a * w3.y; acc[14] += a * w3.z; acc[15] += a * w3.w;
    }
    float4* out4 = reinterpret_cast<float4*>(g_h1 + (long long)(base + row) * HID + col0);
    out4[0] = make_float4(acc[0],  acc[1],  acc[2],  acc[3]);
    out4[1] = make_float4(acc[4],  acc[5],  acc[6],  acc[7]);
    out4[2] = make_float4(acc[8],  acc[9],  acc[10], acc[11]);
    out4[3] = make_float4(acc[12], acc[13], acc[14], acc[15]);
}

// ---------------- K2b: column sums/sumsq of h1 ------------------------------
// 128 threads, one per column; CHUNK rows per block
__global__ void k_stats1() {
    const int CHUNK = 128;
    int col = threadIdx.x;
    int r0 = blockIdx.x * CHUNK;
    int r1 = min(r0 + CHUNK, N_NODES);
    float s = 0.0f, q = 0.0f;
    for (int r = r0; r < r1; r++) {
        float v = g_h1[(long long)r * HID + col];
        s += v;
        q += v * v;
    }
    atomicAdd(&g_stats[col], s);
    atomicAdd(&g_stats[HID + col], q);
}

// ---------------- K3: h2 = relu(bn1(h1)) @ W2 + b2 --------------------------
// block: 128 threads = 16 rows x 8 col-groups of 8
__global__ void k_gemm2(const float* __restrict__ W2,
                        const float* __restrict__ b2,
                        const float* __restrict__ g1,
                        const float* __restrict__ be1) {
    __shared__ float s_W[HID * OUT_DIM];   // 32 KB
    __shared__ float s_b[OUT_DIM];
    __shared__ float s_in[16 * 129];       // padded bn+relu input tile
    __shared__ float s_scale[HID];
    __shared__ float s_shift[HID];

    int tid = threadIdx.x;
    #pragma unroll
    for (int i = 0; i < 64; i++) s_W[tid + i * 128] = W2[tid + i * 128];
    if (tid < OUT_DIM) s_b[tid] = b2[tid];
    // bn1 params
    {
        float invN = 1.0f / (float)N_NODES;
        float mean = g_stats[tid] * invN;
        float var  = g_stats[HID + tid] * invN - mean * mean;
        float sc   = g1[tid] * rsqrtf(var + BN_EPS);
        s_scale[tid] = sc;
        s_shift[tid] = be1[tid] - mean * sc;
    }
    __syncthreads();

    int base = blockIdx.x * 16;
    // stage input tile: 16x128 = 2048 elems, 16 per thread, bn+relu applied
    #pragma unroll
    for (int i = 0; i < 16; i++) {
        int idx = tid + i * 128;
        int r = idx >> 7, k = idx & 127;
        float v = g_h1[(long long)(base + r) * HID + k];
        v = v * s_scale[k] + s_shift[k];
        s_in[r * 129 + k] = fmaxf(v, 0.0f);
    }
    __syncthreads();

    int row = tid >> 3;
    int col0 = (tid & 7) * 8;
    float acc[8];
    #pragma unroll
    for (int j = 0; j < 8; j++) acc[j] = s_b[col0 + j];

    const float* cr = s_in + row * 129;
    #pragma unroll 4
    for (int k = 0; k < HID; k++) {
        float a = cr[k];
        const float4* w4 = reinterpret_cast<const float4*>(s_W + k * OUT_DIM + col0);
        float4 w0 = w4[0], w1 = w4[1];
        acc[0] += a * w0.x; acc[1] += a * w0.y; acc[2] += a * w0.z; acc[3] += a * w0.w;
        acc[4] += a * w1.x; acc[5] += a * w1.y; acc[6] += a * w1.z; acc[7] += a * w1.w;
    }
    float4* out4 = reinterpret_cast<float4*>(g_h2 + (long long)(base + row) * OUT_DIM + col0);
    out4[0] = make_float4(acc[0], acc[1], acc[2], acc[3]);
    out4[1] = make_float4(acc[4], acc[5], acc[6], acc[7]);
}

// ---------------- K3b: column sums/sumsq of h2 ------------------------------
__global__ void k_stats2() {
    const int CHUNK = 64;
    int col = threadIdx.x;    // 64 threads
    int r0 = blockIdx.x * CHUNK;
    int r1 = min(r0 + CHUNK, N_NODES);
    float s = 0.0f, q = 0.0f;
    for (int r = r0; r < r1; r++) {
        float v = g_h2[(long long)r * OUT_DIM + col];
        s += v;
        q += v * v;
    }
    atomicAdd(&g_stats[256 + col], s);
    atomicAdd(&g_stats[320 + col], q);
}

// ---------------- K4: out = bn2(h2) -----------------------------------------
__global__ void k_bn2(const float* __restrict__ g2,
                      const float* __restrict__ be2,
                      float* __restrict__ out) {
    __shared__ float s_scale[OUT_DIM];
    __shared__ float s_shift[OUT_DIM];
    int tid = threadIdx.x;
    if (tid < OUT_DIM) {
        float invN = 1.0f / (float)N_NODES;
        float mean = g_stats[256 + tid] * invN;
        float var  = g_stats[320 + tid] * invN - mean * mean;
        float sc   = g2[tid] * rsqrtf(var + BN_EPS);
        s_scale[tid] = sc;
        s_shift[tid] = be2[tid] - mean * sc;
    }
    __syncthreads();
    long long i = (long long)blockIdx.x * blockDim.x + tid;
    long long tot = (long long)N_NODES * OUT_DIM;
    if (i < tot) {
        int c = (int)(i & 63);
        out[i] = g_h2[i] * s_scale[c] + s_shift[c];
    }
}

// ---------------- launch ----------------------------------------------------
extern "C" void kernel_launch(void* const* d_in, const int* in_sizes, int n_in,
                              void* d_out, int out_size) {
    const float* x    = (const float*)d_in[0];
    const int*   ei   = (const int*)d_in[1];
    const float* eps  = (const float*)d_in[2];
    const float* W1   = (const float*)d_in[3];
    const float* b1   = (const float*)d_in[4];
    const float* g1   = (const float*)d_in[5];
    const float* be1  = (const float*)d_in[6];
    const float* W2   = (const float*)d_in[7];
    const float* b2   = (const float*)d_in[8];
    const float* g2   = (const float*)d_in[9];
    const float* be2  = (const float*)d_in[10];
    float* out = (float*)d_out;

    const int* src = ei;            // edge_index[0]
    const int* dst = ei + N_EDGES;  // edge_index[1]

    // K0: zero ns + stats
    {
        long long tot = (long long)N_NODES * IN_DIM;
        int blocks = (int)((tot + 255) / 256);
        k_zero<<<blocks, 256>>>();
    }
    // K1: scatter-add
    {
        unsigned tot = N_EDGES * 16u;
        int blocks = (int)((tot + 255u) / 256u);
        k_scatter<<<blocks, 256>>>(x, src, dst);
    }
    // K2: GEMM1
    k_gemm1<<<N_NODES / 32, 256>>>(x, eps, W1, b1);
    // K2b: stats of h1
    k_stats1<<<(N_NODES + 127) / 128, 128>>>();
    // K3: BN1+ReLU fused GEMM2
    k_gemm2<<<N_NODES / 16, 128>>>(W2, b2, g1, be1);
    // K3b: stats of h2
    k_stats2<<<(N_NODES + 63) / 64, 64>>>();
    // K4: BN2 -> out
    {
        long long tot = (long long)N_NODES * OUT_DIM;
        int blocks = (int)((tot + 255) / 256);
        k_bn2<<<blocks, 256>>>(g2, be2, out);
    }
}

// round 2
// speedup vs baseline: 1.0469x; 1.0469x over previous
#include <cuda_runtime.h>
#include <cuda_bf16.h>

#define N_NODES 100000
#define N_EDGES 1600000
#define IN_DIM  64
#define HID     128   // 2*OUT_DIM
#define OUT_DIM 64
#define BN_EPS  1e-5f
#define SCAN_B  1024
#define N_SBLK  ((N_NODES + SCAN_B - 1) / SCAN_B)   // 98

// ---------------- scratch (device globals; no allocation allowed) ----------
__device__ float g_ns[N_NODES * IN_DIM];     // combined = (1+eps)x + neighbor_sum
__device__ float g_h1[N_NODES * HID];        // post-GEMM1
__device__ float g_h2[N_NODES * OUT_DIM];    // post-GEMM2
__device__ float g_stats[384];               // sum1[128] sq1[128] sum2[64] sq2[64]
__device__ int   g_cnt[N_NODES];             // degree counts
__device__ int   g_row[N_NODES + 1];         // CSR row pointers (by dst)
__device__ int   g_cur[N_NODES];             // permute cursors
__device__ int   g_esrc[N_EDGES];            // src ids sorted by dst bucket
__device__ int   g_bsum[SCAN_B];             // block sums for scan
__device__ int   g_boff[SCAN_B];             // block offsets

// ---------------- K0: zero counts + stats ----------------------------------
__global__ void k_zero() {
    int i = blockIdx.x * blockDim.x + threadIdx.x;
    if (i < N_NODES) g_cnt[i] = 0;
    if (i < 384) g_stats[i] = 0.0f;
}

// ---------------- K1a: degree histogram -------------------------------------
__global__ void k_hist(const int* __restrict__ dst) {
    int e = blockIdx.x * blockDim.x + threadIdx.x;
    if (e < N_EDGES) atomicAdd(&g_cnt[dst[e]], 1);
}

// ---------------- K1b/c/d: exclusive prefix scan of counts ------------------
__global__ void k_scan1() {
    __shared__ int sh[SCAN_B];
    int b = blockIdx.x, t = threadIdx.x;
    int i = b * SCAN_B + t;
    int v = (i < N_NODES) ? g_cnt[i] : 0;
    sh[t] = v;
    __syncthreads();
    #pragma unroll
    for (int off = 1; off < SCAN_B; off <<= 1) {
        int add = (t >= off) ? sh[t - off] : 0;
        __syncthreads();
        sh[t] += add;
        __syncthreads();
    }
    if (i < N_NODES) g_row[i] = sh[t] - v;   // exclusive, no block offset yet
    if (t == SCAN_B - 1) g_bsum[b] = sh[t];
}

__global__ void k_scan2() {
    __shared__ int sh[128];
    int t = threadIdx.x;
    int v = (t < N_SBLK) ? g_bsum[t] : 0;
    sh[t] = v;
    __syncthreads();
    #pragma unroll
    for (int off = 1; off < 128; off <<= 1) {
        int add = (t >= off) ? sh[t - off] : 0;
        __syncthreads();
        sh[t] += add;
        __syncthreads();
    }
    if (t < N_SBLK) g_boff[t] = sh[t] - v;
}

__global__ void k_scan3() {
    int i = blockIdx.x * blockDim.x + threadIdx.x;
    if (i < N_NODES) {
        int r = g_row[i] + g_boff[i / SCAN_B];
        g_row[i] = r;
        g_cur[i] = r;
    }
    if (i == 0) g_row[N_NODES] = N_EDGES;
}

// ---------------- K1e: bin edges by dst --------------------------------------
__global__ void k_permute(const int* __restrict__ src,
                          const int* __restrict__ dst) {
    int e = blockIdx.x * blockDim.x + threadIdx.x;
    if (e >= N_EDGES) return;
    int d = dst[e];
    int pos = atomicAdd(&g_cur[d], 1);
    g_esrc[pos] = src[e];
}

// ---------------- K1f: gather-aggregate, warp per node -----------------------
// combined[n] = (1+eps)*x[n] + sum_{j in bucket(n)} x[esrc[j]]
__global__ void k_agg(const float* __restrict__ x,
                      const float* __restrict__ eps_p) {
    int warp = (blockIdx.x * blockDim.x + threadIdx.x) >> 5;
    int lane = threadIdx.x & 31;
    if (warp >= N_NODES) return;
    int s = g_row[warp];
    int e = g_row[warp + 1];
    const float2* x2 = reinterpret_cast<const float2*>(x);
    float ax = 0.0f, ay = 0.0f;
    float bx = 0.0f, by = 0.0f;
    int j = s;
    for (; j + 1 < e; j += 2) {
        int s0 = g_esrc[j];
        int s1 = g_esrc[j + 1];
        float2 v0 = x2[(long long)s0 * 32 + lane];
        float2 v1 = x2[(long long)s1 * 32 + lane];
        ax += v0.x; ay += v0.y;
        bx += v1.x; by += v1.y;
    }
    if (j < e) {
        int s0 = g_esrc[j];
        float2 v0 = x2[(long long)s0 * 32 + lane];
        ax += v0.x; ay += v0.y;
    }
    float ep = 1.0f + eps_p[0];
    float2 xv = x2[(long long)warp * 32 + lane];
    float2 out;
    out.x = ax + bx + ep * xv.x;
    out.y = ay + by + ep * xv.y;
    reinterpret_cast<float2*>(g_ns)[(long long)warp * 32 + lane] = out;
}

// ---------------- K2: h1 = combined @ W1 + b1 -------------------------------
// block: 256 threads = 32 rows x 8 col-groups of 16
__global__ void k_gemm1(const float* __restrict__ W1,
                        const float* __restrict__ b1) {
    __shared__ float s_W[IN_DIM * HID];    // 32 KB
    __shared__ float s_b[HID];
    __shared__ float s_c[32 * 65];         // padded combined tile

    int tid = threadIdx.x;
    #pragma unroll
    for (int i = 0; i < 32; i++) s_W[tid + i * 256] = W1[tid + i * 256];
    if (tid < HID) s_b[tid] = b1[tid];

    int base = blockIdx.x * 32;
    #pragma unroll
    for (int i = 0; i < 8; i++) {
        int idx = tid + i * 256;
        int r = idx >> 6, k = idx & 63;
        s_c[r * 65 + k] = g_ns[(long long)(base + r) * 64 + k];
    }
    __syncthreads();

    int row = tid >> 3;
    int col0 = (tid & 7) * 16;
    float acc[16];
    #pragma unroll
    for (int j = 0; j < 16; j++) acc[j] = s_b[col0 + j];

    const float* cr = s_c + row * 65;
    #pragma unroll 4
    for (int k = 0; k < IN_DIM; k++) {
        float a = cr[k];
        const float4* w4 = reinterpret_cast<const float4*>(s_W + k * HID + col0);
        float4 w0 = w4[0], w1 = w4[1], w2 = w4[2], w3 = w4[3];
        acc[0]  += a * w0.x; acc[1]  += a * w0.y; acc[2]  += a * w0.z; acc[3]  += a * w0.w;
        acc[4]  += a * w1.x; acc[5]  += a * w1.y; acc[6]  += a * w1.z; acc[7]  += a * w1.w;
        acc[8]  += a * w2.x; acc[9]  += a * w2.y; acc[10] += a * w2.z; acc[11] += a * w2.w;
        acc[12] += a * w3.x; acc[13] += a * w3.y; acc[14] += a * w3.z; acc[15] += a * w3.w;
    }
    float4* out4 = reinterpret_cast<float4*>(g_h1 + (long long)(base + row) * HID + col0);
    out4[0] = make_float4(acc[0],  acc[1],  acc[2],  acc[3]);
    out4[1] = make_float4(acc[4],  acc[5],  acc[6],  acc[7]);
    out4[2] = make_float4(acc[8],  acc[9],  acc[10], acc[11]);
    out4[3] = make_float4(acc[12], acc[13], acc[14], acc[15]);
}

// ---------------- K2b: column sums/sumsq of h1 ------------------------------
__global__ void k_stats1() {
    const int CHUNK = 128;
    int col = threadIdx.x;
    int r0 = blockIdx.x * CHUNK;
    int r1 = min(r0 + CHUNK, N_NODES);
    float s = 0.0f, q = 0.0f;
    for (int r = r0; r < r1; r++) {
        float v = g_h1[(long long)r * HID + col];
        s += v;
        q += v * v;
    }
    atomicAdd(&g_stats[col], s);
    atomicAdd(&g_stats[HID + col], q);
}

// ---------------- K3: h2 = relu(bn1(h1)) @ W2 + b2 --------------------------
__global__ void k_gemm2(const float* __restrict__ W2,
                        const float* __restrict__ b2,
                        const float* __restrict__ g1,
                        const float* __restrict__ be1) {
    __shared__ float s_W[HID * OUT_DIM];   // 32 KB
    __shared__ float s_b[OUT_DIM];
    __shared__ float s_in[16 * 129];
    __shared__ float s_scale[HID];
    __shared__ float s_shift[HID];

    int tid = threadIdx.x;
    #pragma unroll
    for (int i = 0; i < 64; i++) s_W[tid + i * 128] = W2[tid + i * 128];
    if (tid < OUT_DIM) s_b[tid] = b2[tid];
    {
        float invN = 1.0f / (float)N_NODES;
        float mean = g_stats[tid] * invN;
        float var  = g_stats[HID + tid] * invN - mean * mean;
        float sc   = g1[tid] * rsqrtf(var + BN_EPS);
        s_scale[tid] = sc;
        s_shift[tid] = be1[tid] - mean * sc;
    }
    __syncthreads();

    int base = blockIdx.x * 16;
    #pragma unroll
    for (int i = 0; i < 16; i++) {
        int idx = tid + i * 128;
        int r = idx >> 7, k = idx & 127;
        float v = g_h1[(long long)(base + r) * HID + k];
        v = v * s_scale[k] + s_shift[k];
        s_in[r * 129 + k] = fmaxf(v, 0.0f);
    }
    __syncthreads();

    int row = tid >> 3;
    int col0 = (tid & 7) * 8;
    float acc[8];
    #pragma unroll
    for (int j = 0; j < 8; j++) acc[j] = s_b[col0 + j];

    const float* cr = s_in + row * 129;
    #pragma unroll 4
    for (int k = 0; k < HID; k++) {
        float a = cr[k];
        const float4* w4 = reinterpret_cast<const float4*>(s_W + k * OUT_DIM + col0);
        float4 w0 = w4[0], w1 = w4[1];
        acc[0] += a * w0.x; acc[1] += a * w0.y; acc[2] += a * w0.z; acc[3] += a * w0.w;
        acc[4] += a * w1.x; acc[5] += a * w1.y; acc[6] += a * w1.z; acc[7] += a * w1.w;
    }
    float4* out4 = reinterpret_cast<float4*>(g_h2 + (long long)(base + row) * OUT_DIM + col0);
    out4[0] = make_float4(acc[0], acc[1], acc[2], acc[3]);
    out4[1] = make_float4(acc[4], acc[5], acc[6], acc[7]);
}

// ---------------- K3b: column sums/sumsq of h2 ------------------------------
__global__ void k_stats2() {
    const int CHUNK = 64;
    int col = threadIdx.x;
    int r0 = blockIdx.x * CHUNK;
    int r1 = min(r0 + CHUNK, N_NODES);
    float s = 0.0f, q = 0.0f;
    for (int r = r0; r < r1; r++) {
        float v = g_h2[(long long)r * OUT_DIM + col];
        s += v;
        q += v * v;
    }
    atomicAdd(&g_stats[256 + col], s);
    atomicAdd(&g_stats[320 + col], q);
}

// ---------------- K4: out = bn2(h2) -----------------------------------------
__global__ void k_bn2(const float* __restrict__ g2,
                      const float* __restrict__ be2,
                      float* __restrict__ out) {
    __shared__ float s_scale[OUT_DIM];
    __shared__ float s_shift[OUT_DIM];
    int tid = threadIdx.x;
    if (tid < OUT_DIM) {
        float invN = 1.0f / (float)N_NODES;
        float mean = g_stats[256 + tid] * invN;
        float var  = g_stats[320 + tid] * invN - mean * mean;
        float sc   = g2[tid] * rsqrtf(var + BN_EPS);
        s_scale[tid] = sc;
        s_shift[tid] = be2[tid] - mean * sc;
    }
    __syncthreads();
    long long i = (long long)blockIdx.x * blockDim.x + tid;
    long long tot = (long long)N_NODES * OUT_DIM;
    if (i < tot) {
        int c = (int)(i & 63);
        out[i] = g_h2[i] * s_scale[c] + s_shift[c];
    }
}

// ---------------- launch ----------------------------------------------------
extern "C" void kernel_launch(void* const* d_in, const int* in_sizes, int n_in,
                              void* d_out, int out_size) {
    const float* x    = (const float*)d_in[0];
    const int*   ei   = (const int*)d_in[1];
    const float* eps  = (const float*)d_in[2];
    const float* W1   = (const float*)d_in[3];
    const float* b1   = (const float*)d_in[4];
    const float* g1   = (const float*)d_in[5];
    const float* be1  = (const float*)d_in[6];
    const float* W2   = (const float*)d_in[7];
    const float* b2   = (const float*)d_in[8];
    const float* g2   = (const float*)d_in[9];
    const float* be2  = (const float*)d_in[10];
    float* out = (float*)d_out;

    const int* src = ei;            // edge_index[0]
    const int* dst = ei + N_EDGES;  // edge_index[1]

    k_zero<<<(N_NODES + 255) / 256, 256>>>();
    k_hist<<<(N_EDGES + 255) / 256, 256>>>(dst);
    k_scan1<<<N_SBLK, SCAN_B>>>();
    k_scan2<<<1, 128>>>();
    k_scan3<<<(N_NODES + 255) / 256, 256>>>();
    k_permute<<<(N_EDGES + 255) / 256, 256>>>(src, dst);
    k_agg<<<(N_NODES * 32 + 255) / 256, 256>>>(x, eps);
    k_gemm1<<<N_NODES / 32, 256>>>(W1, b1);
    k_stats1<<<(N_NODES + 127) / 128, 128>>>();
    k_gemm2<<<N_NODES / 16, 128>>>(W2, b2, g1, be1);
    k_stats2<<<(N_NODES + 63) / 64, 64>>>();
    k_bn2<<<(int)(((long long)N_NODES * OUT_DIM + 255) / 256), 256>>>(g2, be2, out);
}

// round 3
// speedup vs baseline: 1.0476x; 1.0007x over previous
#include <cuda_runtime.h>
#include <cuda_bf16.h>

#define N_NODES 100000
#define N_EDGES 1600000
#define IN_DIM  64
#define HID     128   // 2*OUT_DIM
#define OUT_DIM 64
#define BN_EPS  1e-5f
#define SCAN_B  1024
#define N_SBLK  ((N_NODES + SCAN_B - 1) / SCAN_B)   // 98

// ---------------- scratch (device globals; no allocation allowed) ----------
__device__ float g_ns[N_NODES * IN_DIM];     // combined = (1+eps)x + neighbor_sum
__device__ float g_h1[N_NODES * HID];        // post-GEMM1
__device__ float g_h2[N_NODES * OUT_DIM];    // post-GEMM2
__device__ float g_stats[384];               // sum1[128] sq1[128] sum2[64] sq2[64]
__device__ int   g_cnt[N_NODES];             // degree counts
__device__ int   g_row[N_NODES + 1];         // CSR row pointers (by dst)
__device__ int   g_cur[N_NODES];             // permute cursors
__device__ int   g_esrc[N_EDGES];            // src ids sorted by dst bucket
__device__ int   g_bsum[SCAN_B];             // block sums for scan
__device__ int   g_boff[SCAN_B];             // block offsets

// ---------------- K0: zero counts + stats ----------------------------------
__global__ void k_zero() {
    int i = blockIdx.x * blockDim.x + threadIdx.x;
    if (i < N_NODES) g_cnt[i] = 0;
    if (i < 384) g_stats[i] = 0.0f;
}

// ---------------- K1a: degree histogram -------------------------------------
__global__ void k_hist(const int* __restrict__ dst) {
    int e = blockIdx.x * blockDim.x + threadIdx.x;
    if (e < N_EDGES) atomicAdd(&g_cnt[dst[e]], 1);
}

// ---------------- K1b/c/d: exclusive prefix scan of counts ------------------
__global__ void k_scan1() {
    __shared__ int sh[SCAN_B];
    int b = blockIdx.x, t = threadIdx.x;
    int i = b * SCAN_B + t;
    int v = (i < N_NODES) ? g_cnt[i] : 0;
    sh[t] = v;
    __syncthreads();
    #pragma unroll
    for (int off = 1; off < SCAN_B; off <<= 1) {
        int add = (t >= off) ? sh[t - off] : 0;
        __syncthreads();
        sh[t] += add;
        __syncthreads();
    }
    if (i < N_NODES) g_row[i] = sh[t] - v;   // exclusive, no block offset yet
    if (t == SCAN_B - 1) g_bsum[b] = sh[t];
}

__global__ void k_scan2() {
    __shared__ int sh[128];
    int t = threadIdx.x;
    int v = (t < N_SBLK) ? g_bsum[t] : 0;
    sh[t] = v;
    __syncthreads();
    #pragma unroll
    for (int off = 1; off < 128; off <<= 1) {
        int add = (t >= off) ? sh[t - off] : 0;
        __syncthreads();
        sh[t] += add;
        __syncthreads();
    }
    if (t < N_SBLK) g_boff[t] = sh[t] - v;
}

__global__ void k_scan3() {
    int i = blockIdx.x * blockDim.x + threadIdx.x;
    if (i < N_NODES) {
        int r = g_row[i] + g_boff[i / SCAN_B];
        g_row[i] = r;
        g_cur[i] = r;
    }
    if (i == 0) g_row[N_NODES] = N_EDGES;
}

// ---------------- K1e: bin edges by dst --------------------------------------
__global__ void k_permute(const int* __restrict__ src,
                          const int* __restrict__ dst) {
    int e = blockIdx.x * blockDim.x + threadIdx.x;
    if (e >= N_EDGES) return;
    int d = dst[e];
    int pos = atomicAdd(&g_cur[d], 1);
    g_esrc[pos] = src[e];
}

// ---------------- K1f: gather-aggregate, warp per node -----------------------
// combined[n] = (1+eps)*x[n] + sum_{j in bucket(n)} x[esrc[j]]
__global__ void k_agg(const float* __restrict__ x,
                      const float* __restrict__ eps_p) {
    int warp = (blockIdx.x * blockDim.x + threadIdx.x) >> 5;
    int lane = threadIdx.x & 31;
    if (warp >= N_NODES) return;
    int s = g_row[warp];
    int e = g_row[warp + 1];
    const float2* x2 = reinterpret_cast<const float2*>(x);
    float ax = 0.0f, ay = 0.0f;
    float bx = 0.0f, by = 0.0f;
    int j = s;
    for (; j + 1 < e; j += 2) {
        int s0 = g_esrc[j];
        int s1 = g_esrc[j + 1];
        float2 v0 = x2[(long long)s0 * 32 + lane];
        float2 v1 = x2[(long long)s1 * 32 + lane];
        ax += v0.x; ay += v0.y;
        bx += v1.x; by += v1.y;
    }
    if (j < e) {
        int s0 = g_esrc[j];
        float2 v0 = x2[(long long)s0 * 32 + lane];
        ax += v0.x; ay += v0.y;
    }
    float ep = 1.0f + eps_p[0];
    float2 xv = x2[(long long)warp * 32 + lane];
    float2 out;
    out.x = ax + bx + ep * xv.x;
    out.y = ay + by + ep * xv.y;
    reinterpret_cast<float2*>(g_ns)[(long long)warp * 32 + lane] = out;
}

// ---------------- K2: h1 = combined @ W1 + b1 -------------------------------
// block: 256 threads = 32 rows x 8 col-groups of 16
__global__ void k_gemm1(const float* __restrict__ W1,
                        const float* __restrict__ b1) {
    __shared__ float s_W[IN_DIM * HID];    // 32 KB
    __shared__ float s_b[HID];
    __shared__ float s_c[32 * 65];         // padded combined tile

    int tid = threadIdx.x;
    #pragma unroll
    for (int i = 0; i < 32; i++) s_W[tid + i * 256] = W1[tid + i * 256];
    if (tid < HID) s_b[tid] = b1[tid];

    int base = blockIdx.x * 32;
    #pragma unroll
    for (int i = 0; i < 8; i++) {
        int idx = tid + i * 256;
        int r = idx >> 6, k = idx & 63;
        s_c[r * 65 + k] = g_ns[(long long)(base + r) * 64 + k];
    }
    __syncthreads();

    int row = tid >> 3;
    int col0 = (tid & 7) * 16;
    float acc[16];
    #pragma unroll
    for (int j = 0; j < 16; j++) acc[j] = s_b[col0 + j];

    const float* cr = s_c + row * 65;
    #pragma unroll 4
    for (int k = 0; k < IN_DIM; k++) {
        float a = cr[k];
        const float4* w4 = reinterpret_cast<const float4*>(s_W + k * HID + col0);
        float4 w0 = w4[0], w1 = w4[1], w2 = w4[2], w3 = w4[3];
        acc[0]  += a * w0.x; acc[1]  += a * w0.y; acc[2]  += a * w0.z; acc[3]  += a * w0.w;
        acc[4]  += a * w1.x; acc[5]  += a * w1.y; acc[6]  += a * w1.z; acc[7]  += a * w1.w;
        acc[8]  += a * w2.x; acc[9]  += a * w2.y; acc[10] += a * w2.z; acc[11] += a * w2.w;
        acc[12] += a * w3.x; acc[13] += a * w3.y; acc[14] += a * w3.z; acc[15] += a * w3.w;
    }
    float4* out4 = reinterpret_cast<float4*>(g_h1 + (long long)(base + row) * HID + col0);
    out4[0] = make_float4(acc[0],  acc[1],  acc[2],  acc[3]);
    out4[1] = make_float4(acc[4],  acc[5],  acc[6],  acc[7]);
    out4[2] = make_float4(acc[8],  acc[9],  acc[10], acc[11]);
    out4[3] = make_float4(acc[12], acc[13], acc[14], acc[15]);
}

// ---------------- K2b: column sums/sumsq of h1 ------------------------------
__global__ void k_stats1() {
    const int CHUNK = 128;
    int col = threadIdx.x;
    int r0 = blockIdx.x * CHUNK;
    int r1 = min(r0 + CHUNK, N_NODES);
    float s = 0.0f, q = 0.0f;
    for (int r = r0; r < r1; r++) {
        float v = g_h1[(long long)r * HID + col];
        s += v;
        q += v * v;
    }
    atomicAdd(&g_stats[col], s);
    atomicAdd(&g_stats[HID + col], q);
}

// ---------------- K3: h2 = relu(bn1(h1)) @ W2 + b2 --------------------------
__global__ void k_gemm2(const float* __restrict__ W2,
                        const float* __restrict__ b2,
                        const float* __restrict__ g1,
                        const float* __restrict__ be1) {
    __shared__ float s_W[HID * OUT_DIM];   // 32 KB
    __shared__ float s_b[OUT_DIM];
    __shared__ float s_in[16 * 129];
    __shared__ float s_scale[HID];
    __shared__ float s_shift[HID];

    int tid = threadIdx.x;
    #pragma unroll
    for (int i = 0; i < 64; i++) s_W[tid + i * 128] = W2[tid + i * 128];
    if (tid < OUT_DIM) s_b[tid] = b2[tid];
    {
        float invN = 1.0f / (float)N_NODES;
        float mean = g_stats[tid] * invN;
        float var  = g_stats[HID + tid] * invN - mean * mean;
        float sc   = g1[tid] * rsqrtf(var + BN_EPS);
        s_scale[tid] = sc;
        s_shift[tid] = be1[tid] - mean * sc;
    }
    __syncthreads();

    int base = blockIdx.x * 16;
    #pragma unroll
    for (int i = 0; i < 16; i++) {
        int idx = tid + i * 128;
        int r = idx >> 7, k = idx & 127;
        float v = g_h1[(long long)(base + r) * HID + k];
        v = v * s_scale[k] + s_shift[k];
        s_in[r * 129 + k] = fmaxf(v, 0.0f);
    }
    __syncthreads();

    int row = tid >> 3;
    int col0 = (tid & 7) * 8;
    float acc[8];
    #pragma unroll
    for (int j = 0; j < 8; j++) acc[j] = s_b[col0 + j];

    const float* cr = s_in + row * 129;
    #pragma unroll 4
    for (int k = 0; k < HID; k++) {
        float a = cr[k];
        const float4* w4 = reinterpret_cast<const float4*>(s_W + k * OUT_DIM + col0);
        float4 w0 = w4[0], w1 = w4[1];
        acc[0] += a * w0.x; acc[1] += a * w0.y; acc[2] += a * w0.z; acc[3] += a * w0.w;
        acc[4] += a * w1.x; acc[5] += a * w1.y; acc[6] += a * w1.z; acc[7] += a * w1.w;
    }
    float4* out4 = reinterpret_cast<float4*>(g_h2 + (long long)(base + row) * OUT_DIM + col0);
    out4[0] = make_float4(acc[0], acc[1], acc[2], acc[3]);
    out4[1] = make_float4(acc[4], acc[5], acc[6], acc[7]);
}

// ---------------- K3b: column sums/sumsq of h2 ------------------------------
__global__ void k_stats2() {
    const int CHUNK = 64;
    int col = threadIdx.x;
    int r0 = blockIdx.x * CHUNK;
    int r1 = min(r0 + CHUNK, N_NODES);
    float s = 0.0f, q = 0.0f;
    for (int r = r0; r < r1; r++) {
        float v = g_h2[(long long)r * OUT_DIM + col];
        s += v;
        q += v * v;
    }
    atomicAdd(&g_stats[256 + col], s);
    atomicAdd(&g_stats[320 + col], q);
}

// ---------------- K4: out = bn2(h2) -----------------------------------------
__global__ void k_bn2(const float* __restrict__ g2,
                      const float* __restrict__ be2,
                      float* __restrict__ out) {
    __shared__ float s_scale[OUT_DIM];
    __shared__ float s_shift[OUT_DIM];
    int tid = threadIdx.x;
    if (tid < OUT_DIM) {
        float invN = 1.0f / (float)N_NODES;
        float mean = g_stats[256 + tid] * invN;
        float var  = g_stats[320 + tid] * invN - mean * mean;
        float sc   = g2[tid] * rsqrtf(var + BN_EPS);
        s_scale[tid] = sc;
        s_shift[tid] = be2[tid] - mean * sc;
    }
    __syncthreads();
    long long i = (long long)blockIdx.x * blockDim.x + tid;
    long long tot = (long long)N_NODES * OUT_DIM;
    if (i < tot) {
        int c = (int)(i & 63);
        out[i] = g_h2[i] * s_scale[c] + s_shift[c];
    }
}

// ---------------- launch ----------------------------------------------------
extern "C" void kernel_launch(void* const* d_in, const int* in_sizes, int n_in,
                              void* d_out, int out_size) {
    const float* x    = (const float*)d_in[0];
    const int*   ei   = (const int*)d_in[1];
    const float* eps  = (const float*)d_in[2];
    const float* W1   = (const float*)d_in[3];
    const float* b1   = (const float*)d_in[4];
    const float* g1   = (const float*)d_in[5];
    const float* be1  = (const float*)d_in[6];
    const float* W2   = (const float*)d_in[7];
    const float* b2   = (const float*)d_in[8];
    const float* g2   = (const float*)d_in[9];
    const float* be2  = (const float*)d_in[10];
    float* out = (float*)d_out;

    const int* src = ei;            // edge_index[0]
    const int* dst = ei + N_EDGES;  // edge_index[1]

    k_zero<<<(N_NODES + 255) / 256, 256>>>();
    k_hist<<<(N_EDGES + 255) / 256, 256>>>(dst);
    k_scan1<<<N_SBLK, SCAN_B>>>();
    k_scan2<<<1, 128>>>();
    k_scan3<<<(N_NODES + 255) / 256, 256>>>();
    k_permute<<<(N_EDGES + 255) / 256, 256>>>(src, dst);
    k_agg<<<(N_NODES * 32 + 255) / 256, 256>>>(x, eps);
    k_gemm1<<<N_NODES / 32, 256>>>(W1, b1);
    k_stats1<<<(N_NODES + 127) / 128, 128>>>();
    k_gemm2<<<N_NODES / 16, 128>>>(W2, b2, g1, be1);
    k_stats2<<<(N_NODES + 63) / 64, 64>>>();
    k_bn2<<<(int)(((long long)N_NODES * OUT_DIM + 255) / 256), 256>>>(g2, be2, out);
}

// round 4
// speedup vs baseline: 1.0478x; 1.0002x over previous
#include <cuda_runtime.h>
#include <cuda_bf16.h>

#define N_NODES 100000
#define N_EDGES 1600000
#define IN_DIM  64
#define HID     128   // 2*OUT_DIM
#define OUT_DIM 64
#define BN_EPS  1e-5f
#define SCAN_B  1024
#define N_SBLK  ((N_NODES + SCAN_B - 1) / SCAN_B)   // 98

// ---------------- scratch (device globals; no allocation allowed) ----------
__device__ float g_ns[N_NODES * IN_DIM];     // combined = (1+eps)x + neighbor_sum
__device__ float g_h1[N_NODES * HID];        // post-GEMM1
__device__ float g_h2[N_NODES * OUT_DIM];    // post-GEMM2
__device__ float g_stats[384];               // sum1[128] sq1[128] sum2[64] sq2[64]
__device__ int   g_cnt[N_NODES];             // degree counts
__device__ int   g_row[N_NODES + 1];         // CSR row pointers (by dst)
__device__ int   g_cur[N_NODES];             // permute cursors
__device__ int   g_esrc[N_EDGES];            // src ids sorted by dst bucket
__device__ int   g_bsum[SCAN_B];             // block sums for scan
__device__ int   g_boff[SCAN_B];             // block offsets

// ---------------- K0: zero counts + stats ----------------------------------
__global__ void k_zero() {
    int i = blockIdx.x * blockDim.x + threadIdx.x;
    if (i < N_NODES) g_cnt[i] = 0;
    if (i < 384) g_stats[i] = 0.0f;
}

// ---------------- K1a: degree histogram -------------------------------------
__global__ void k_hist(const int* __restrict__ dst) {
    int e = blockIdx.x * blockDim.x + threadIdx.x;
    if (e < N_EDGES) atomicAdd(&g_cnt[dst[e]], 1);
}

// ---------------- K1b/c/d: exclusive prefix scan of counts ------------------
__global__ void k_scan1() {
    __shared__ int sh[SCAN_B];
    int b = blockIdx.x, t = threadIdx.x;
    int i = b * SCAN_B + t;
    int v = (i < N_NODES) ? g_cnt[i] : 0;
    sh[t] = v;
    __syncthreads();
    #pragma unroll
    for (int off = 1; off < SCAN_B; off <<= 1) {
        int add = (t >= off) ? sh[t - off] : 0;
        __syncthreads();
        sh[t] += add;
        __syncthreads();
    }
    if (i < N_NODES) g_row[i] = sh[t] - v;   // exclusive, no block offset yet
    if (t == SCAN_B - 1) g_bsum[b] = sh[t];
}

__global__ void k_scan2() {
    __shared__ int sh[128];
    int t = threadIdx.x;
    int v = (t < N_SBLK) ? g_bsum[t] : 0;
    sh[t] = v;
    __syncthreads();
    #pragma unroll
    for (int off = 1; off < 128; off <<= 1) {
        int add = (t >= off) ? sh[t - off] : 0;
        __syncthreads();
        sh[t] += add;
        __syncthreads();
    }
    if (t < N_SBLK) g_boff[t] = sh[t] - v;
}

__global__ void k_scan3() {
    int i = blockIdx.x * blockDim.x + threadIdx.x;
    if (i < N_NODES) {
        int r = g_row[i] + g_boff[i / SCAN_B];
        g_row[i] = r;
        g_cur[i] = r;
    }
    if (i == 0) g_row[N_NODES] = N_EDGES;
}

// ---------------- K1e: bin edges by dst --------------------------------------
__global__ void k_permute(const int* __restrict__ src,
                          const int* __restrict__ dst) {
    int e = blockIdx.x * blockDim.x + threadIdx.x;
    if (e >= N_EDGES) return;
    int d = dst[e];
    int pos = atomicAdd(&g_cur[d], 1);
    g_esrc[pos] = src[e];
}

// ---------------- K1f: gather-aggregate, warp per node -----------------------
// combined[n] = (1+eps)*x[n] + sum_{j in bucket(n)} x[esrc[j]]
__global__ void k_agg(const float* __restrict__ x,
                      const float* __restrict__ eps_p) {
    int warp = (blockIdx.x * blockDim.x + threadIdx.x) >> 5;
    int lane = threadIdx.x & 31;
    if (warp >= N_NODES) return;
    int s = g_row[warp];
    int e = g_row[warp + 1];
    const float2* x2 = reinterpret_cast<const float2*>(x);
    float ax = 0.0f, ay = 0.0f;
    float bx = 0.0f, by = 0.0f;
    int j = s;
    for (; j + 1 < e; j += 2) {
        int s0 = g_esrc[j];
        int s1 = g_esrc[j + 1];
        float2 v0 = x2[(long long)s0 * 32 + lane];
        float2 v1 = x2[(long long)s1 * 32 + lane];
        ax += v0.x; ay += v0.y;
        bx += v1.x; by += v1.y;
    }
    if (j < e) {
        int s0 = g_esrc[j];
        float2 v0 = x2[(long long)s0 * 32 + lane];
        ax += v0.x; ay += v0.y;
    }
    float ep = 1.0f + eps_p[0];
    float2 xv = x2[(long long)warp * 32 + lane];
    float2 out;
    out.x = ax + bx + ep * xv.x;
    out.y = ay + by + ep * xv.y;
    reinterpret_cast<float2*>(g_ns)[(long long)warp * 32 + lane] = out;
}

// ---------------- K2: h1 = combined @ W1 + b1 -------------------------------
// block: 256 threads = 32 rows x 8 col-groups of 16
__global__ void k_gemm1(const float* __restrict__ W1,
                        const float* __restrict__ b1) {
    __shared__ float s_W[IN_DIM * HID];    // 32 KB
    __shared__ float s_b[HID];
    __shared__ float s_c[32 * 65];         // padded combined tile

    int tid = threadIdx.x;
    #pragma unroll
    for (int i = 0; i < 32; i++) s_W[tid + i * 256] = W1[tid + i * 256];
    if (tid < HID) s_b[tid] = b1[tid];

    int base = blockIdx.x * 32;
    #pragma unroll
    for (int i = 0; i < 8; i++) {
        int idx = tid + i * 256;
        int r = idx >> 6, k = idx & 63;
        s_c[r * 65 + k] = g_ns[(long long)(base + r) * 64 + k];
    }
    __syncthreads();

    int row = tid >> 3;
    int col0 = (tid & 7) * 16;
    float acc[16];
    #pragma unroll
    for (int j = 0; j < 16; j++) acc[j] = s_b[col0 + j];

    const float* cr = s_c + row * 65;
    #pragma unroll 4
    for (int k = 0; k < IN_DIM; k++) {
        float a = cr[k];
        const float4* w4 = reinterpret_cast<const float4*>(s_W + k * HID + col0);
        float4 w0 = w4[0], w1 = w4[1], w2 = w4[2], w3 = w4[3];
        acc[0]  += a * w0.x; acc[1]  += a * w0.y; acc[2]  += a * w0.z; acc[3]  += a * w0.w;
        acc[4]  += a * w1.x; acc[5]  += a * w1.y; acc[6]  += a * w1.z; acc[7]  += a * w1.w;
        acc[8]  += a * w2.x; acc[9]  += a * w2.y; acc[10] += a * w2.z; acc[11] += a * w2.w;
        acc[12] += a * w3.x; acc[13] += a * w3.y; acc[14] += a * w3.z; acc[15] += a * w3.w;
    }
    float4* out4 = reinterpret_cast<float4*>(g_h1 + (long long)(base + row) * HID + col0);
    out4[0] = make_float4(acc[0],  acc[1],  acc[2],  acc[3]);
    out4[1] = make_float4(acc[4],  acc[5],  acc[6],  acc[7]);
    out4[2] = make_float4(acc[8],  acc[9],  acc[10], acc[11]);
    out4[3] = make_float4(acc[12], acc[13], acc[14], acc[15]);
}

// ---------------- K2b: column sums/sumsq of h1 ------------------------------
__global__ void k_stats1() {
    const int CHUNK = 128;
    int col = threadIdx.x;
    int r0 = blockIdx.x * CHUNK;
    int r1 = min(r0 + CHUNK, N_NODES);
    float s = 0.0f, q = 0.0f;
    for (int r = r0; r < r1; r++) {
        float v = g_h1[(long long)r * HID + col];
        s += v;
        q += v * v;
    }
    atomicAdd(&g_stats[col], s);
    atomicAdd(&g_stats[HID + col], q);
}

// ---------------- K3: h2 = relu(bn1(h1)) @ W2 + b2 --------------------------
__global__ void k_gemm2(const float* __restrict__ W2,
                        const float* __restrict__ b2,
                        const float* __restrict__ g1,
                        const float* __restrict__ be1) {
    __shared__ float s_W[HID * OUT_DIM];   // 32 KB
    __shared__ float s_b[OUT_DIM];
    __shared__ float s_in[16 * 129];
    __shared__ float s_scale[HID];
    __shared__ float s_shift[HID];

    int tid = threadIdx.x;
    #pragma unroll
    for (int i = 0; i < 64; i++) s_W[tid + i * 128] = W2[tid + i * 128];
    if (tid < OUT_DIM) s_b[tid] = b2[tid];
    {
        float invN = 1.0f / (float)N_NODES;
        float mean = g_stats[tid] * invN;
        float var  = g_stats[HID + tid] * invN - mean * mean;
        float sc   = g1[tid] * rsqrtf(var + BN_EPS);
        s_scale[tid] = sc;
        s_shift[tid] = be1[tid] - mean * sc;
    }
    __syncthreads();

    int base = blockIdx.x * 16;
    #pragma unroll
    for (int i = 0; i < 16; i++) {
        int idx = tid + i * 128;
        int r = idx >> 7, k = idx & 127;
        float v = g_h1[(long long)(base + r) * HID + k];
        v = v * s_scale[k] + s_shift[k];
        s_in[r * 129 + k] = fmaxf(v, 0.0f);
    }
    __syncthreads();

    int row = tid >> 3;
    int col0 = (tid & 7) * 8;
    float acc[8];
    #pragma unroll
    for (int j = 0; j < 8; j++) acc[j] = s_b[col0 + j];

    const float* cr = s_in + row * 129;
    #pragma unroll 4
    for (int k = 0; k < HID; k++) {
        float a = cr[k];
        const float4* w4 = reinterpret_cast<const float4*>(s_W + k * OUT_DIM + col0);
        float4 w0 = w4[0], w1 = w4[1];
        acc[0] += a * w0.x; acc[1] += a * w0.y; acc[2] += a * w0.z; acc[3] += a * w0.w;
        acc[4] += a * w1.x; acc[5] += a * w1.y; acc[6] += a * w1.z; acc[7] += a * w1.w;
    }
    float4* out4 = reinterpret_cast<float4*>(g_h2 + (long long)(base + row) * OUT_DIM + col0);
    out4[0] = make_float4(acc[0], acc[1], acc[2], acc[3]);
    out4[1] = make_float4(acc[4], acc[5], acc[6], acc[7]);
}

// ---------------- K3b: column sums/sumsq of h2 ------------------------------
__global__ void k_stats2() {
    const int CHUNK = 64;
    int col = threadIdx.x;
    int r0 = blockIdx.x * CHUNK;
    int r1 = min(r0 + CHUNK, N_NODES);
    float s = 0.0f, q = 0.0f;
    for (int r = r0; r < r1; r++) {
        float v = g_h2[(long long)r * OUT_DIM + col];
        s += v;
        q += v * v;
    }
    atomicAdd(&g_stats[256 + col], s);
    atomicAdd(&g_stats[320 + col], q);
}

// ---------------- K4: out = bn2(h2) -----------------------------------------
__global__ void k_bn2(const float* __restrict__ g2,
                      const float* __restrict__ be2,
                      float* __restrict__ out) {
    __shared__ float s_scale[OUT_DIM];
    __shared__ float s_shift[OUT_DIM];
    int tid = threadIdx.x;
    if (tid < OUT_DIM) {
        float invN = 1.0f / (float)N_NODES;
        float mean = g_stats[256 + tid] * invN;
        float var  = g_stats[320 + tid] * invN - mean * mean;
        float sc   = g2[tid] * rsqrtf(var + BN_EPS);
        s_scale[tid] = sc;
        s_shift[tid] = be2[tid] - mean * sc;
    }
    __syncthreads();
    long long i = (long long)blockIdx.x * blockDim.x + tid;
    long long tot = (long long)N_NODES * OUT_DIM;
    if (i < tot) {
        int c = (int)(i & 63);
        out[i] = g_h2[i] * s_scale[c] + s_shift[c];
    }
}

// ---------------- launch ----------------------------------------------------
extern "C" void kernel_launch(void* const* d_in, const int* in_sizes, int n_in,
                              void* d_out, int out_size) {
    const float* x    = (const float*)d_in[0];
    const int*   ei   = (const int*)d_in[1];
    const float* eps  = (const float*)d_in[2];
    const float* W1   = (const float*)d_in[3];
    const float* b1   = (const float*)d_in[4];
    const float* g1   = (const float*)d_in[5];
    const float* be1  = (const float*)d_in[6];
    const float* W2   = (const float*)d_in[7];
    const float* b2   = (const float*)d_in[8];
    const float* g2   = (const float*)d_in[9];
    const float* be2  = (const float*)d_in[10];
    float* out = (float*)d_out;

    const int* src = ei;            // edge_index[0]
    const int* dst = ei + N_EDGES;  // edge_index[1]

    k_zero<<<(N_NODES + 255) / 256, 256>>>();
    k_hist<<<(N_EDGES + 255) / 256, 256>>>(dst);
    k_scan1<<<N_SBLK, SCAN_B>>>();
    k_scan2<<<1, 128>>>();
    k_scan3<<<(N_NODES + 255) / 256, 256>>>();
    k_permute<<<(N_EDGES + 255) / 256, 256>>>(src, dst);
    k_agg<<<(N_NODES * 32 + 255) / 256, 256>>>(x, eps);
    k_gemm1<<<N_NODES / 32, 256>>>(W1, b1);
    k_stats1<<<(N_NODES + 127) / 128, 128>>>();
    k_gemm2<<<N_NODES / 16, 128>>>(W2, b2, g1, be1);
    k_stats2<<<(N_NODES + 63) / 64, 64>>>();
    k_bn2<<<(int)(((long long)N_NODES * OUT_DIM + 255) / 256), 256>>>(g2, be2, out);
}

// round 5
// speedup vs baseline: 2.6037x; 2.4850x over previous
#include <cuda_runtime.h>
#include <cuda_bf16.h>

#define N_NODES 100000
#define N_EDGES 1600000
#define IN_DIM  64
#define HID     128   // 2*OUT_DIM
#define OUT_DIM 64
#define BN_EPS  1e-5f
#define SCAN_B  1024
#define N_SBLK  ((N_NODES + SCAN_B - 1) / SCAN_B)   // 98

// ---------------- scratch (device globals; no allocation allowed) ----------
__device__ float g_ns[N_NODES * IN_DIM];     // combined = (1+eps)x + neighbor_sum
__device__ float g_h1[N_NODES * HID];        // post-GEMM1
__device__ float g_h2[N_NODES * OUT_DIM];    // post-GEMM2
__device__ float g_stats[384];               // sum1[128] sq1[128] sum2[64] sq2[64]
__device__ int   g_cnt[N_NODES];             // degree counts
__device__ int   g_row[N_NODES + 1];         // CSR row pointers (by dst)
__device__ int   g_cur[N_NODES];             // permute cursors
__device__ int   g_esrc[N_EDGES];            // src ids sorted by dst bucket
__device__ int   g_bsum[SCAN_B];             // block sums for scan
__device__ int   g_boff[SCAN_B];             // block offsets

// ---------------- K0: zero counts + stats ----------------------------------
__global__ void k_zero() {
    int i = blockIdx.x * blockDim.x + threadIdx.x;
    if (i < N_NODES) g_cnt[i] = 0;
    if (i < 384) g_stats[i] = 0.0f;
}

// ---------------- K1a: degree histogram -------------------------------------
__global__ void k_hist(const int* __restrict__ dst) {
    int e = blockIdx.x * blockDim.x + threadIdx.x;
    if (e < N_EDGES) atomicAdd(&g_cnt[dst[e]], 1);
}

// ---------------- K1b/c/d: exclusive prefix scan of counts ------------------
__global__ void k_scan1() {
    __shared__ int sh[SCAN_B];
    int b = blockIdx.x, t = threadIdx.x;
    int i = b * SCAN_B + t;
    int v = (i < N_NODES) ? g_cnt[i] : 0;
    sh[t] = v;
    __syncthreads();
    #pragma unroll
    for (int off = 1; off < SCAN_B; off <<= 1) {
        int add = (t >= off) ? sh[t - off] : 0;
        __syncthreads();
        sh[t] += add;
        __syncthreads();
    }
    if (i < N_NODES) g_row[i] = sh[t] - v;
    if (t == SCAN_B - 1) g_bsum[b] = sh[t];
}

__global__ void k_scan2() {
    __shared__ int sh[128];
    int t = threadIdx.x;
    int v = (t < N_SBLK) ? g_bsum[t] : 0;
    sh[t] = v;
    __syncthreads();
    #pragma unroll
    for (int off = 1; off < 128; off <<= 1) {
        int add = (t >= off) ? sh[t - off] : 0;
        __syncthreads();
        sh[t] += add;
        __syncthreads();
    }
    if (t < N_SBLK) g_boff[t] = sh[t] - v;
}

__global__ void k_scan3() {
    int i = blockIdx.x * blockDim.x + threadIdx.x;
    if (i < N_NODES) {
        int r = g_row[i] + g_boff[i / SCAN_B];
        g_row[i] = r;
        g_cur[i] = r;
    }
    if (i == 0) g_row[N_NODES] = N_EDGES;
}

// ---------------- K1e: bin edges by dst --------------------------------------
__global__ void k_permute(const int* __restrict__ src,
                          const int* __restrict__ dst) {
    int e = blockIdx.x * blockDim.x + threadIdx.x;
    if (e >= N_EDGES) return;
    int d = dst[e];
    int pos = atomicAdd(&g_cur[d], 1);
    g_esrc[pos] = src[e];
}

// ---------------- K1f: gather-aggregate, warp per node (4-deep MLP) ----------
__global__ void k_agg(const float* __restrict__ x,
                      const float* __restrict__ eps_p) {
    int warp = (blockIdx.x * blockDim.x + threadIdx.x) >> 5;
    int lane = threadIdx.x & 31;
    if (warp >= N_NODES) return;
    int s = g_row[warp];
    int e = g_row[warp + 1];
    const float2* x2 = reinterpret_cast<const float2*>(x);
    float a0x = 0.f, a0y = 0.f, a1x = 0.f, a1y = 0.f;
    float a2x = 0.f, a2y = 0.f, a3x = 0.f, a3y = 0.f;
    int j = s;
    for (; j + 3 < e; j += 4) {
        int s0 = g_esrc[j],     s1 = g_esrc[j + 1];
        int s2 = g_esrc[j + 2], s3 = g_esrc[j + 3];
        float2 v0 = x2[(long long)s0 * 32 + lane];
        float2 v1 = x2[(long long)s1 * 32 + lane];
        float2 v2 = x2[(long long)s2 * 32 + lane];
        float2 v3 = x2[(long long)s3 * 32 + lane];
        a0x += v0.x; a0y += v0.y;
        a1x += v1.x; a1y += v1.y;
        a2x += v2.x; a2y += v2.y;
        a3x += v3.x; a3y += v3.y;
    }
    for (; j < e; j++) {
        int s0 = g_esrc[j];
        float2 v0 = x2[(long long)s0 * 32 + lane];
        a0x += v0.x; a0y += v0.y;
    }
    float ep = 1.0f + eps_p[0];
    float2 xv = x2[(long long)warp * 32 + lane];
    float2 out;
    out.x = (a0x + a1x) + (a2x + a3x) + ep * xv.x;
    out.y = (a0y + a1y) + (a2y + a3y) + ep * xv.y;
    reinterpret_cast<float2*>(g_ns)[(long long)warp * 32 + lane] = out;
}

// ---------------- K2: h1 = combined @ W1 + b1 -------------------------------
// block: 256 threads = 8 warps. Tile: 32 rows x 128 cols.
// Warp w owns cols [w*16, w*16+16) for ALL 32 rows; lane = row.
// Weight loads are warp-uniform (broadcast, conflict-free).
// Input loads s_c[lane*65+k]: stride 65 == 1 mod 32 -> conflict-free.
__global__ void k_gemm1(const float* __restrict__ W1,
                        const float* __restrict__ b1) {
    __shared__ float s_W[IN_DIM * HID];    // 32 KB, row k major
    __shared__ float s_b[HID];
    __shared__ float s_c[32 * 65];         // padded input tile

    int tid = threadIdx.x;
    #pragma unroll
    for (int i = 0; i < 32; i++) s_W[tid + i * 256] = W1[tid + i * 256];
    if (tid < HID) s_b[tid] = b1[tid];

    int base = blockIdx.x * 32;
    #pragma unroll
    for (int i = 0; i < 8; i++) {
        int idx = tid + i * 256;
        int r = idx >> 6, k = idx & 63;
        s_c[r * 65 + k] = g_ns[(long long)(base + r) * 64 + k];
    }
    __syncthreads();

    int w    = tid >> 5;          // warp id -> col group
    int lane = tid & 31;          // lane -> row
    int c0   = w * 16;

    float acc[16];
    {
        const float4* b4 = reinterpret_cast<const float4*>(s_b + c0);
        float4 v0 = b4[0], v1 = b4[1], v2 = b4[2], v3 = b4[3];
        acc[0]=v0.x; acc[1]=v0.y; acc[2]=v0.z; acc[3]=v0.w;
        acc[4]=v1.x; acc[5]=v1.y; acc[6]=v1.z; acc[7]=v1.w;
        acc[8]=v2.x; acc[9]=v2.y; acc[10]=v2.z; acc[11]=v2.w;
        acc[12]=v3.x; acc[13]=v3.y; acc[14]=v3.z; acc[15]=v3.w;
    }

    const float* cr = s_c + lane * 65;
    #pragma unroll 8
    for (int k = 0; k < IN_DIM; k++) {
        float a = cr[k];
        const float4* w4 = reinterpret_cast<const float4*>(s_W + k * HID + c0);
        float4 w0 = w4[0], w1 = w4[1], w2 = w4[2], w3 = w4[3];
        acc[0]  += a * w0.x; acc[1]  += a * w0.y; acc[2]  += a * w0.z; acc[3]  += a * w0.w;
        acc[4]  += a * w1.x; acc[5]  += a * w1.y; acc[6]  += a * w1.z; acc[7]  += a * w1.w;
        acc[8]  += a * w2.x; acc[9]  += a * w2.y; acc[10] += a * w2.z; acc[11] += a * w2.w;
        acc[12] += a * w3.x; acc[13] += a * w3.y; acc[14] += a * w3.z; acc[15] += a * w3.w;
    }
    float4* out4 = reinterpret_cast<float4*>(g_h1 + (long long)(base + lane) * HID + c0);
    out4[0] = make_float4(acc[0],  acc[1],  acc[2],  acc[3]);
    out4[1] = make_float4(acc[4],  acc[5],  acc[6],  acc[7]);
    out4[2] = make_float4(acc[8],  acc[9],  acc[10], acc[11]);
    out4[3] = make_float4(acc[12], acc[13], acc[14], acc[15]);
}

// ---------------- K2b: column sums/sumsq of h1 ------------------------------
__global__ void k_stats1() {
    const int CHUNK = 128;
    int col = threadIdx.x;
    int r0 = blockIdx.x * CHUNK;
    int r1 = min(r0 + CHUNK, N_NODES);
    float s = 0.0f, q = 0.0f;
    for (int r = r0; r < r1; r++) {
        float v = g_h1[(long long)r * HID + col];
        s += v;
        q += v * v;
    }
    atomicAdd(&g_stats[col], s);
    atomicAdd(&g_stats[HID + col], q);
}

// ---------------- K3: h2 = relu(bn1(h1)) @ W2 + b2 --------------------------
// block: 128 threads = 4 warps. Tile: 32 rows x 64 cols.
// Warp w owns cols [w*16, w*16+16); lane = row. Conflict-free as in k_gemm1.
__global__ void k_gemm2(const float* __restrict__ W2,
                        const float* __restrict__ b2,
                        const float* __restrict__ g1,
                        const float* __restrict__ be1) {
    __shared__ float s_W[HID * OUT_DIM];   // 32 KB
    __shared__ float s_b[OUT_DIM];
    __shared__ float s_in[32 * 129];       // padded bn+relu input tile
    __shared__ float s_scale[HID];
    __shared__ float s_shift[HID];

    int tid = threadIdx.x;
    #pragma unroll
    for (int i = 0; i < 64; i++) s_W[tid + i * 128] = W2[tid + i * 128];
    if (tid < OUT_DIM) s_b[tid] = b2[tid];
    {
        float invN = 1.0f / (float)N_NODES;
        float mean = g_stats[tid] * invN;
        float var  = g_stats[HID + tid] * invN - mean * mean;
        float sc   = g1[tid] * rsqrtf(var + BN_EPS);
        s_scale[tid] = sc;
        s_shift[tid] = be1[tid] - mean * sc;
    }
    __syncthreads();

    int base = blockIdx.x * 32;
    #pragma unroll
    for (int i = 0; i < 32; i++) {
        int idx = tid + i * 128;
        int r = idx >> 7, k = idx & 127;
        float v = g_h1[(long long)(base + r) * HID + k];
        v = v * s_scale[k] + s_shift[k];
        s_in[r * 129 + k] = fmaxf(v, 0.0f);
    }
    __syncthreads();

    int w    = tid >> 5;
    int lane = tid & 31;
    int c0   = w * 16;

    float acc[16];
    {
        const float4* b4 = reinterpret_cast<const float4*>(s_b + c0);
        float4 v0 = b4[0], v1 = b4[1], v2 = b4[2], v3 = b4[3];
        acc[0]=v0.x; acc[1]=v0.y; acc[2]=v0.z; acc[3]=v0.w;
        acc[4]=v1.x; acc[5]=v1.y; acc[6]=v1.z; acc[7]=v1.w;
        acc[8]=v2.x; acc[9]=v2.y; acc[10]=v2.z; acc[11]=v2.w;
        acc[12]=v3.x; acc[13]=v3.y; acc[14]=v3.z; acc[15]=v3.w;
    }

    const float* cr = s_in + lane * 129;
    #pragma unroll 8
    for (int k = 0; k < HID; k++) {
        float a = cr[k];
        const float4* w4 = reinterpret_cast<const float4*>(s_W + k * OUT_DIM + c0);
        float4 w0 = w4[0], w1 = w4[1], w2 = w4[2], w3 = w4[3];
        acc[0]  += a * w0.x; acc[1]  += a * w0.y; acc[2]  += a * w0.z; acc[3]  += a * w0.w;
        acc[4]  += a * w1.x; acc[5]  += a * w1.y; acc[6]  += a * w1.z; acc[7]  += a * w1.w;
        acc[8]  += a * w2.x; acc[9]  += a * w2.y; acc[10] += a * w2.z; acc[11] += a * w2.w;
        acc[12] += a * w3.x; acc[13] += a * w3.y; acc[14] += a * w3.z; acc[15] += a * w3.w;
    }
    float4* out4 = reinterpret_cast<float4*>(g_h2 + (long long)(base + lane) * OUT_DIM + c0);
    out4[0] = make_float4(acc[0],  acc[1],  acc[2],  acc[3]);
    out4[1] = make_float4(acc[4],  acc[5],  acc[6],  acc[7]);
    out4[2] = make_float4(acc[8],  acc[9],  acc[10], acc[11]);
    out4[3] = make_float4(acc[12], acc[13], acc[14], acc[15]);
}

// ---------------- K3b: column sums/sumsq of h2 ------------------------------
__global__ void k_stats2() {
    const int CHUNK = 64;
    int col = threadIdx.x;
    int r0 = blockIdx.x * CHUNK;
    int r1 = min(r0 + CHUNK, N_NODES);
    float s = 0.0f, q = 0.0f;
    for (int r = r0; r < r1; r++) {
        float v = g_h2[(long long)r * OUT_DIM + col];
        s += v;
        q += v * v;
    }
    atomicAdd(&g_stats[256 + col], s);
    atomicAdd(&g_stats[320 + col], q);
}

// ---------------- K4: out = bn2(h2) -----------------------------------------
__global__ void k_bn2(const float* __restrict__ g2,
                      const float* __restrict__ be2,
                      float* __restrict__ out) {
    __shared__ float s_scale[OUT_DIM];
    __shared__ float s_shift[OUT_DIM];
    int tid = threadIdx.x;
    if (tid < OUT_DIM) {
        float invN = 1.0f / (float)N_NODES;
        float mean = g_stats[256 + tid] * invN;
        float var  = g_stats[320 + tid] * invN - mean * mean;
        float sc   = g2[tid] * rsqrtf(var + BN_EPS);
        s_scale[tid] = sc;
        s_shift[tid] = be2[tid] - mean * sc;
    }
    __syncthreads();
    long long i = (long long)blockIdx.x * blockDim.x + tid;
    long long tot = (long long)N_NODES * OUT_DIM;
    if (i < tot) {
        int c = (int)(i & 63);
        out[i] = g_h2[i] * s_scale[c] + s_shift[c];
    }
}

// ---------------- launch ----------------------------------------------------
extern "C" void kernel_launch(void* const* d_in, const int* in_sizes, int n_in,
                              void* d_out, int out_size) {
    const float* x    = (const float*)d_in[0];
    const int*   ei   = (const int*)d_in[1];
    const float* eps  = (const float*)d_in[2];
    const float* W1   = (const float*)d_in[3];
    const float* b1   = (const float*)d_in[4];
    const float* g1   = (const float*)d_in[5];
    const float* be1  = (const float*)d_in[6];
    const float* W2   = (const float*)d_in[7];
    const float* b2   = (const float*)d_in[8];
    const float* g2   = (const float*)d_in[9];
    const float* be2  = (const float*)d_in[10];
    float* out = (float*)d_out;

    const int* src = ei;            // edge_index[0]
    const int* dst = ei + N_EDGES;  // edge_index[1]

    k_zero<<<(N_NODES + 255) / 256, 256>>>();
    k_hist<<<(N_EDGES + 255) / 256, 256>>>(dst);
    k_scan1<<<N_SBLK, SCAN_B>>>();
    k_scan2<<<1, 128>>>();
    k_scan3<<<(N_NODES + 255) / 256, 256>>>();
    k_permute<<<(N_EDGES + 255) / 256, 256>>>(src, dst);
    k_agg<<<(N_NODES * 32 + 255) / 256, 256>>>(x, eps);
    k_gemm1<<<N_NODES / 32, 256>>>(W1, b1);
    k_stats1<<<(N_NODES + 127) / 128, 128>>>();
    k_gemm2<<<N_NODES / 32, 128>>>(W2, b2, g1, be1);
    k_stats2<<<(N_NODES + 63) / 64, 64>>>();
    k_bn2<<<(int)(((long long)N_NODES * OUT_DIM + 255) / 256), 256>>>(g2, be2, out);
}